// round 1
// baseline (speedup 1.0000x reference)
#include <cuda_runtime.h>
#include <math.h>

#define NN 1024
#define MM 64
#define LDA 1040          // row stride of scratch matrices (floats)
#define PTW 1032          // panel smem row stride (floats)
#define NTH 256

// 64 matrices of 1024x1040 fp32 scratch (static device global: allowed)
__device__ float g_cov[(size_t)MM * NN * LDA];

typedef unsigned long long ull;

__device__ __forceinline__ ull pack2(float lo, float hi) {
    ull r; asm("mov.b64 %0, {%1, %2};" : "=l"(r) : "f"(lo), "f"(hi)); return r;
}
__device__ __forceinline__ void fma2(ull& d, ull a, ull b) {
    asm("fma.rn.f32x2 %0, %1, %2, %0;" : "+l"(d) : "l"(a), "l"(b));
}
__device__ __forceinline__ float2 unpack2(ull v) {
    float2 f; asm("mov.b64 {%0, %1}, %2;" : "=f"(f.x), "=f"(f.y) : "l"(v)); return f;
}

// stable softplus + DELTA, matching jax.nn.softplus(x) + 1e-7
__device__ __forceinline__ float sp_(float x) {
    return fmaxf(x, 0.f) + log1pf(expf(-fabsf(x))) + 1e-7f;
}
__device__ __forceinline__ float log_normal_(float v, float mean, float s, float eps) {
    const float C = -0.91893853320467274178f;
    float d = v - mean;
    return -d * d / (2.f * s * s + eps) - logf(s) + C;
}
__device__ __forceinline__ float log_lognormal_(float v, float mean, float s, float eps) {
    const float C = -0.91893853320467274178f;
    float lv = logf(v);
    float d = lv - mean;
    return -d * d / (2.f * s * s + eps) - lv - logf(s) + C;
}

// smem layout (floats):
//   Pt   [32*PTW]   panel, k-major (reused as xs0/xs1 during build, rhs during solve)
//   Lkk  [32*33]
//   rinv [32]
//   scal [8]   : 0 beta, 1 sigma2, 2 eta, 3 lsZ, 4 lsN, 5 (lp - lq), 6 logdet_acc
//   red  [256]
#define SMEM_FLOATS (32 * PTW + 32 * 33 + 32 + 8 + 256)

extern "C" __global__ void __launch_bounds__(NTH, 1)
vi_kernel(const float* __restrict__ x, const float* __restrict__ y,
          const float* __restrict__ z,
          const float* qbm, const float* qbs, const float* qsm, const float* qss,
          const float* qem, const float* qes, const float* qzm, const float* qzs,
          const float* qnm, const float* qns, float* __restrict__ out)
{
    extern __shared__ float sm[];
    float* Pt   = sm;
    float* Lkk  = sm + 32 * PTW;
    float* rinv = Lkk + 32 * 33;
    float* scal = rinv + 32;
    float* red  = scal + 8;

    const int tid = threadIdx.x;
    const int m   = blockIdx.x;
    float* cov = g_cov + (size_t)m * NN * LDA;

    // ---- scalar terms (thread 0) ----
    if (tid == 0) {
        float s0 = sp_(sqrtf(logf(2.f)));   // default prior scale
        float z0 = z[m * 5 + 0], z1 = z[m * 5 + 1], z2 = z[m * 5 + 2];
        float z3 = z[m * 5 + 3], z4 = z[m * 5 + 4];
        float sps = sp_(*qss), spb = sp_(*qbs), spe = sp_(*qes);
        float spz = sp_(*qzs), spn = sp_(*qns);
        float sigma2 = expf(z0 * sps + *qsm);
        float beta   = z1 * spb + *qbm;
        float eta    = expf(z2 * spe + *qem);
        float lsZ    = expf(z3 * spz + *qzm);
        float lsN    = expf(z4 * spn + *qnm);
        float lp = log_normal_(beta, 0.f, 1.f, 1e-5f)
                 + log_lognormal_(sigma2, 1.f, s0, 1e-6f)
                 + log_lognormal_(eta,    1.f, s0, 1e-6f)
                 + log_lognormal_(lsZ,    1.f, s0, 1e-6f)
                 + log_lognormal_(lsN,    1.f, s0, 1e-6f);
        float lq = log_normal_(beta, *qbm, spb, 1e-5f)
                 + log_lognormal_(sigma2, *qsm, sps, 1e-6f)
                 + log_lognormal_(eta,    *qem, spe, 1e-6f)
                 + log_lognormal_(lsZ,    *qzm, spz, 1e-6f)
                 + log_lognormal_(lsN,    *qnm, spn, 1e-6f);
        scal[0] = beta; scal[1] = sigma2; scal[2] = eta;
        scal[3] = lsZ;  scal[4] = lsN;    scal[5] = lp - lq;
        scal[6] = 0.f;
    }
    __syncthreads();
    const float beta = scal[0], sigma2 = scal[1], eta = scal[2];

    // ---- stage scaled x into smem ----
    {
        float lsZ = scal[3], lsN = scal[4];
        float* xs0 = Pt;
        float* xs1 = Pt + NN;
        for (int i = tid; i < NN; i += NTH) {
            xs0[i] = x[2 * i]     / lsZ;
            xs1[i] = x[2 * i + 1] / lsN;
        }
    }
    __syncthreads();

    // ---- build lower-triangular cov ----
    {
        const float* xs0 = Pt;
        const float* xs1 = Pt + NN;
        for (int i = tid; i < NN; i += NTH) {
            float xi0 = xs0[i], xi1 = xs1[i];
            float* row = cov + (size_t)i * LDA;
            for (int j = 0; j < i; ++j) {
                float d0 = xi0 - xs0[j];
                float d1 = xi1 - xs1[j];
                row[j] = eta * __expf(-0.5f * (d0 * d0 + d1 * d1));
            }
            row[i] = eta + sigma2;
        }
    }
    __syncthreads();

    // ---- blocked Cholesky, NB=32, 32 steps ----
    for (int kb = 0; kb < 32; ++kb) {
        const int k0 = kb * 32;

        // load diag block (lower) into smem, zero upper
        for (int idx = tid; idx < 1024; idx += NTH) {
            int r = idx >> 5, c = idx & 31;
            Lkk[r * 33 + c] = (c <= r) ? cov[(size_t)(k0 + r) * LDA + k0 + c] : 0.f;
        }
        __syncthreads();

        // factor 32x32 diag block: warp 0, registers + shuffles
        if (tid < 32) {
            const int lane = tid;
            float a[32];
            #pragma unroll
            for (int j = 0; j < 32; ++j) a[j] = Lkk[lane * 33 + j];
            #pragma unroll
            for (int j = 0; j < 32; ++j) {
                float dj = __shfl_sync(0xffffffffu, a[j], j);
                float sj = sqrtf(dj);
                float lrj = (lane == j) ? sj : a[j] / sj;
                a[j] = lrj;
                #pragma unroll
                for (int c = j + 1; c < 32; ++c) {
                    float lcj = __shfl_sync(0xffffffffu, lrj, c);
                    a[c] -= lrj * lcj;
                }
            }
            #pragma unroll
            for (int j = 0; j < 32; ++j)
                if (j <= lane) {
                    Lkk[lane * 33 + j] = a[j];
                    cov[(size_t)(k0 + lane) * LDA + k0 + j] = a[j];
                }
            rinv[lane] = 1.f / a[lane];
            float ld = logf(a[lane]);
            #pragma unroll
            for (int o = 16; o; o >>= 1) ld += __shfl_xor_sync(0xffffffffu, ld, o);
            if (lane == 0) scal[6] += ld;
        }
        __syncthreads();

        const int nt = NN - k0 - 32;
        if (nt > 0) {
            // ---- panel solve: rows below, 2 rows per thread-iteration ----
            for (int it0 = 0; it0 < nt; it0 += 2 * NTH) {
                int it1 = it0 + tid, it2 = it0 + NTH + tid;
                bool v1 = it1 < nt, v2 = it2 < nt;
                int ri1 = v1 ? it1 : 0;
                int ri2 = v2 ? it2 : 0;
                const float* r1 = cov + (size_t)(k0 + 32 + ri1) * LDA + k0;
                const float* r2 = cov + (size_t)(k0 + 32 + ri2) * LDA + k0;
                float a1[32], a2[32];
                #pragma unroll
                for (int w = 0; w < 8; ++w) {
                    float4 q1 = ((const float4*)r1)[w];
                    float4 q2 = ((const float4*)r2)[w];
                    a1[4*w] = q1.x; a1[4*w+1] = q1.y; a1[4*w+2] = q1.z; a1[4*w+3] = q1.w;
                    a2[4*w] = q2.x; a2[4*w+1] = q2.y; a2[4*w+2] = q2.z; a2[4*w+3] = q2.w;
                }
                #pragma unroll
                for (int j = 0; j < 32; ++j) {
                    float s1 = a1[j], s2 = a2[j];
                    #pragma unroll
                    for (int p = 0; p < j; ++p) {
                        float l = Lkk[j * 33 + p];
                        s1 -= a1[p] * l;
                        s2 -= a2[p] * l;
                    }
                    float rj = rinv[j];
                    a1[j] = s1 * rj;
                    a2[j] = s2 * rj;
                }
                if (v1) {
                    float* wr = cov + (size_t)(k0 + 32 + it1) * LDA + k0;
                    #pragma unroll
                    for (int w = 0; w < 8; ++w)
                        ((float4*)wr)[w] = make_float4(a1[4*w], a1[4*w+1], a1[4*w+2], a1[4*w+3]);
                    #pragma unroll
                    for (int p = 0; p < 32; ++p) Pt[p * PTW + it1] = a1[p];
                }
                if (v2) {
                    float* wr = cov + (size_t)(k0 + 32 + it2) * LDA + k0;
                    #pragma unroll
                    for (int w = 0; w < 8; ++w)
                        ((float4*)wr)[w] = make_float4(a2[4*w], a2[4*w+1], a2[4*w+2], a2[4*w+3]);
                    #pragma unroll
                    for (int p = 0; p < 32; ++p) Pt[p * PTW + it2] = a2[p];
                }
            }
            __syncthreads();

            // ---- trailing SYRK update: cov[i][j] -= sum_p P[i][p] P[j][p] ----
            const int ntile = (nt + 127) >> 7;
            const int tx = tid & 15, ty = tid >> 4;
            for (int tjb = 0; tjb < ntile; ++tjb)
                for (int tib = tjb; tib < ntile; ++tib) {
                    const int il = tib * 128 + ty * 8;
                    const int jl = tjb * 128 + tx * 8;
                    ull acc[8][4];
                    #pragma unroll
                    for (int r = 0; r < 8; ++r)
                        #pragma unroll
                        for (int s = 0; s < 4; ++s) acc[r][s] = 0ull;

                    #pragma unroll 4
                    for (int p = 0; p < 32; ++p) {
                        const float4* bp = (const float4*)(Pt + p * PTW);
                        float4 av0 = bp[il >> 2], av1 = bp[(il >> 2) + 1];
                        float4 bv0 = bp[jl >> 2], bv1 = bp[(jl >> 2) + 1];
                        ull b2[4] = { pack2(bv0.x, bv0.y), pack2(bv0.z, bv0.w),
                                      pack2(bv1.x, bv1.y), pack2(bv1.z, bv1.w) };
                        float aa[8] = { av0.x, av0.y, av0.z, av0.w,
                                        av1.x, av1.y, av1.z, av1.w };
                        #pragma unroll
                        for (int r = 0; r < 8; ++r) {
                            ull a2 = pack2(aa[r], aa[r]);
                            fma2(acc[r][0], a2, b2[0]);
                            fma2(acc[r][1], a2, b2[1]);
                            fma2(acc[r][2], a2, b2[2]);
                            fma2(acc[r][3], a2, b2[3]);
                        }
                    }
                    const int g0 = k0 + 32;
                    #pragma unroll
                    for (int r = 0; r < 8; ++r) {
                        const int i = il + r;
                        if (i < nt) {
                            float* row = cov + (size_t)(g0 + i) * LDA + g0;
                            if (jl + 7 <= i && jl + 7 < nt) {
                                float4 c0 = *(float4*)(row + jl);
                                float4 c1 = *(float4*)(row + jl + 4);
                                float2 u;
                                u = unpack2(acc[r][0]); c0.x -= u.x; c0.y -= u.y;
                                u = unpack2(acc[r][1]); c0.z -= u.x; c0.w -= u.y;
                                u = unpack2(acc[r][2]); c1.x -= u.x; c1.y -= u.y;
                                u = unpack2(acc[r][3]); c1.z -= u.x; c1.w -= u.y;
                                *(float4*)(row + jl)     = c0;
                                *(float4*)(row + jl + 4) = c1;
                            } else {
                                #pragma unroll
                                for (int s = 0; s < 4; ++s) {
                                    float2 u = unpack2(acc[r][s]);
                                    int j = jl + 2 * s;
                                    if (j     <= i && j     < nt) row[j]     -= u.x;
                                    if (j + 1 <= i && j + 1 < nt) row[j + 1] -= u.y;
                                }
                            }
                        }
                    }
                }
        }
        __syncthreads();
    }

    // ---- forward substitution: L sol = (y - beta) ----
    float* rhs = Pt;
    for (int i = tid; i < NN; i += NTH) rhs[i] = y[i] - beta;
    __syncthreads();

    for (int kb = 0; kb < 32; ++kb) {
        const int k0 = kb * 32;
        if (tid < 32) {
            const int lane = tid;
            const float* lrow = cov + (size_t)(k0 + lane) * LDA + k0;
            float lr[32];
            #pragma unroll
            for (int w = 0; w < 8; ++w) {
                float4 q = ((const float4*)lrow)[w];
                lr[4*w] = q.x; lr[4*w+1] = q.y; lr[4*w+2] = q.z; lr[4*w+3] = q.w;
            }
            float t = rhs[k0 + lane];
            #pragma unroll
            for (int j = 0; j < 32; ++j) {
                if (lane == j) t /= lr[j];
                float sj = __shfl_sync(0xffffffffu, t, j);
                if (lane > j) t -= sj * lr[j];
            }
            rhs[k0 + lane] = t;
        }
        __syncthreads();
        for (int i = k0 + 32 + tid; i < NN; i += NTH) {
            const float* row = cov + (size_t)i * LDA + k0;
            float acc = 0.f;
            #pragma unroll
            for (int w = 0; w < 8; ++w) {
                float4 c4 = ((const float4*)row)[w];
                acc += c4.x * rhs[k0 + 4*w]     + c4.y * rhs[k0 + 4*w + 1]
                     + c4.z * rhs[k0 + 4*w + 2] + c4.w * rhs[k0 + 4*w + 3];
            }
            rhs[i] -= acc;
        }
        __syncthreads();
    }

    // ---- quad reduction + output ----
    float q = 0.f;
    for (int i = tid; i < NN; i += NTH) q += rhs[i] * rhs[i];
    red[tid] = q;
    __syncthreads();
    for (int s = 128; s; s >>= 1) {
        if (tid < s) red[tid] += red[tid + s];
        __syncthreads();
    }
    if (tid == 0) {
        float logdet = 2.f * scal[6];
        const float LN2PI = 1.8378770664093453f;
        float ll = -0.5f * (red[0] + logdet + 1024.f * LN2PI);
        out[m] = ll + scal[5];
    }
}

extern "C" void kernel_launch(void* const* d_in, const int* in_sizes, int n_in,
                              void* d_out, int out_size)
{
    (void)in_sizes; (void)n_in; (void)out_size;
    const float* x = (const float*)d_in[0];
    const float* y = (const float*)d_in[1];
    const float* z = (const float*)d_in[2];

    const int smem_bytes = SMEM_FLOATS * (int)sizeof(float);
    cudaFuncSetAttribute(vi_kernel, cudaFuncAttributeMaxDynamicSharedMemorySize, smem_bytes);

    vi_kernel<<<MM, NTH, smem_bytes>>>(
        x, y, z,
        (const float*)d_in[3], (const float*)d_in[4],
        (const float*)d_in[5], (const float*)d_in[6],
        (const float*)d_in[7], (const float*)d_in[8],
        (const float*)d_in[9], (const float*)d_in[10],
        (const float*)d_in[11], (const float*)d_in[12],
        (float*)d_out);
}

// round 2
// speedup vs baseline: 1.4030x; 1.4030x over previous
#include <cuda_runtime.h>
#include <math.h>

#define NN 1024
#define MM 64
#define LDA 1040          // row stride of scratch matrices (floats)
#define PTW 1032          // panel smem row stride (floats)
#define NTH 512

// 64 matrices of 1024x1040 fp32 scratch (static device global: allowed)
__device__ float g_cov[(size_t)MM * NN * LDA];

typedef unsigned long long ull;

__device__ __forceinline__ ull pack2(float lo, float hi) {
    ull r; asm("mov.b64 %0, {%1, %2};" : "=l"(r) : "f"(lo), "f"(hi)); return r;
}
__device__ __forceinline__ void fma2(ull& d, ull a, ull b) {
    asm("fma.rn.f32x2 %0, %1, %2, %0;" : "+l"(d) : "l"(a), "l"(b));
}
__device__ __forceinline__ float2 unpack2(ull v) {
    float2 f; asm("mov.b64 {%0, %1}, %2;" : "=f"(f.x), "=f"(f.y) : "l"(v)); return f;
}

// stable softplus + DELTA, matching jax.nn.softplus(x) + 1e-7
__device__ __forceinline__ float sp_(float x) {
    return fmaxf(x, 0.f) + log1pf(expf(-fabsf(x))) + 1e-7f;
}
__device__ __forceinline__ float log_normal_(float v, float mean, float s, float eps) {
    const float C = -0.91893853320467274178f;
    float d = v - mean;
    return -d * d / (2.f * s * s + eps) - logf(s) + C;
}
__device__ __forceinline__ float log_lognormal_(float v, float mean, float s, float eps) {
    const float C = -0.91893853320467274178f;
    float lv = logf(v);
    float d = lv - mean;
    return -d * d / (2.f * s * s + eps) - lv - logf(s) + C;
}

// smem layout (floats):
//   Pt   [32*PTW]   panel, k-major (reused as xs0/xs1 during build, rhs during solve)
//   Lkk  [32*33]
//   rinv [32]
//   scal [8]
//   red  [NTH]
#define SMEM_FLOATS (32 * PTW + 32 * 33 + 32 + 8 + NTH)

extern "C" __global__ void __launch_bounds__(NTH, 1)
vi_kernel(const float* __restrict__ x, const float* __restrict__ y,
          const float* __restrict__ z,
          const float* qbm, const float* qbs, const float* qsm, const float* qss,
          const float* qem, const float* qes, const float* qzm, const float* qzs,
          const float* qnm, const float* qns, float* __restrict__ out)
{
    extern __shared__ float sm[];
    float* Pt   = sm;
    float* Lkk  = sm + 32 * PTW;
    float* rinv = Lkk + 32 * 33;
    float* scal = rinv + 32;
    float* red  = scal + 8;

    const int tid = threadIdx.x;
    const int m   = blockIdx.x;
    float* cov = g_cov + (size_t)m * NN * LDA;

    // ---- scalar terms (thread 0) ----
    if (tid == 0) {
        float s0 = sp_(sqrtf(logf(2.f)));   // default prior scale
        float z0 = z[m * 5 + 0], z1 = z[m * 5 + 1], z2 = z[m * 5 + 2];
        float z3 = z[m * 5 + 3], z4 = z[m * 5 + 4];
        float sps = sp_(*qss), spb = sp_(*qbs), spe = sp_(*qes);
        float spz = sp_(*qzs), spn = sp_(*qns);
        float sigma2 = expf(z0 * sps + *qsm);
        float beta   = z1 * spb + *qbm;
        float eta    = expf(z2 * spe + *qem);
        float lsZ    = expf(z3 * spz + *qzm);
        float lsN    = expf(z4 * spn + *qnm);
        float lp = log_normal_(beta, 0.f, 1.f, 1e-5f)
                 + log_lognormal_(sigma2, 1.f, s0, 1e-6f)
                 + log_lognormal_(eta,    1.f, s0, 1e-6f)
                 + log_lognormal_(lsZ,    1.f, s0, 1e-6f)
                 + log_lognormal_(lsN,    1.f, s0, 1e-6f);
        float lq = log_normal_(beta, *qbm, spb, 1e-5f)
                 + log_lognormal_(sigma2, *qsm, sps, 1e-6f)
                 + log_lognormal_(eta,    *qem, spe, 1e-6f)
                 + log_lognormal_(lsZ,    *qzm, spz, 1e-6f)
                 + log_lognormal_(lsN,    *qnm, spn, 1e-6f);
        scal[0] = beta; scal[1] = sigma2; scal[2] = eta;
        scal[3] = lsZ;  scal[4] = lsN;    scal[5] = lp - lq;
        scal[6] = 0.f;
    }
    __syncthreads();
    const float beta = scal[0], sigma2 = scal[1], eta = scal[2];

    // ---- stage scaled x into smem ----
    {
        float lsZ = scal[3], lsN = scal[4];
        float* xs0 = Pt;
        float* xs1 = Pt + NN;
        for (int i = tid; i < NN; i += NTH) {
            xs0[i] = x[2 * i]     / lsZ;
            xs1[i] = x[2 * i + 1] / lsN;
        }
    }
    __syncthreads();

    // ---- build lower-triangular cov ----
    {
        const float* xs0 = Pt;
        const float* xs1 = Pt + NN;
        for (int i = tid; i < NN; i += NTH) {
            float xi0 = xs0[i], xi1 = xs1[i];
            float* row = cov + (size_t)i * LDA;
            for (int j = 0; j < i; ++j) {
                float d0 = xi0 - xs0[j];
                float d1 = xi1 - xs1[j];
                row[j] = eta * __expf(-0.5f * (d0 * d0 + d1 * d1));
            }
            row[i] = eta + sigma2;
        }
    }
    __syncthreads();

    // ---- blocked Cholesky, NB=32, 32 steps ----
    for (int kb = 0; kb < 32; ++kb) {
        const int k0 = kb * 32;

        // load diag block (lower) into smem, zero upper
        for (int idx = tid; idx < 1024; idx += NTH) {
            int r = idx >> 5, c = idx & 31;
            Lkk[r * 33 + c] = (c <= r) ? cov[(size_t)(k0 + r) * LDA + k0 + c] : 0.f;
        }
        __syncthreads();

        // factor 32x32 diag block: warp 0, registers + shuffles
        if (tid < 32) {
            const int lane = tid;
            float a[32];
            #pragma unroll
            for (int j = 0; j < 32; ++j) a[j] = Lkk[lane * 33 + j];
            #pragma unroll
            for (int j = 0; j < 32; ++j) {
                float dj = __shfl_sync(0xffffffffu, a[j], j);
                float sj = sqrtf(dj);
                float lrj = (lane == j) ? sj : a[j] / sj;
                a[j] = lrj;
                #pragma unroll
                for (int c = j + 1; c < 32; ++c) {
                    float lcj = __shfl_sync(0xffffffffu, lrj, c);
                    a[c] -= lrj * lcj;
                }
            }
            #pragma unroll
            for (int j = 0; j < 32; ++j)
                if (j <= lane) {
                    Lkk[lane * 33 + j] = a[j];
                    cov[(size_t)(k0 + lane) * LDA + k0 + j] = a[j];
                }
            rinv[lane] = 1.f / a[lane];
            float ld = logf(a[lane]);
            #pragma unroll
            for (int o = 16; o; o >>= 1) ld += __shfl_xor_sync(0xffffffffu, ld, o);
            if (lane == 0) scal[6] += ld;
        }
        __syncthreads();

        const int nt = NN - k0 - 32;
        if (nt > 0) {
            // ---- panel solve: one row per thread ----
            for (int it = tid; it < nt; it += NTH) {
                const float* r1 = cov + (size_t)(k0 + 32 + it) * LDA + k0;
                float a1[32];
                #pragma unroll
                for (int w = 0; w < 8; ++w) {
                    float4 q1 = ((const float4*)r1)[w];
                    a1[4*w] = q1.x; a1[4*w+1] = q1.y; a1[4*w+2] = q1.z; a1[4*w+3] = q1.w;
                }
                #pragma unroll
                for (int j = 0; j < 32; ++j) {
                    float s1 = a1[j];
                    #pragma unroll
                    for (int p = 0; p < j; ++p)
                        s1 -= a1[p] * Lkk[j * 33 + p];
                    a1[j] = s1 * rinv[j];
                }
                float* wr = cov + (size_t)(k0 + 32 + it) * LDA + k0;
                #pragma unroll
                for (int w = 0; w < 8; ++w)
                    ((float4*)wr)[w] = make_float4(a1[4*w], a1[4*w+1], a1[4*w+2], a1[4*w+3]);
                #pragma unroll
                for (int p = 0; p < 32; ++p) Pt[p * PTW + it] = a1[p];
            }
            __syncthreads();

            // ---- trailing SYRK: two concurrent 256-thread tile groups ----
            const int ntile = (nt + 127) >> 7;
            const int npair = ntile * (ntile + 1) / 2;
            const int grp = tid >> 8;           // 0 or 1
            const int t   = tid & 255;
            const int tx = t & 15, ty = t >> 4;
            for (int pair = grp; pair < npair; pair += 2) {
                // decode linear pair -> (tjb, tib) over lower triangle
                int tjb = 0, rem = pair;
                while (rem >= ntile - tjb) { rem -= ntile - tjb; ++tjb; }
                int tib = tjb + rem;

                const int il = tib * 128 + ty * 8;
                const int jl = tjb * 128 + tx * 8;
                ull acc[8][4];
                #pragma unroll
                for (int r = 0; r < 8; ++r)
                    #pragma unroll
                    for (int s = 0; s < 4; ++s) acc[r][s] = 0ull;

                #pragma unroll 8
                for (int p = 0; p < 32; ++p) {
                    const float4* bp = (const float4*)(Pt + p * PTW);
                    float4 av0 = bp[il >> 2], av1 = bp[(il >> 2) + 1];
                    float4 bv0 = bp[jl >> 2], bv1 = bp[(jl >> 2) + 1];
                    ull b2[4] = { pack2(bv0.x, bv0.y), pack2(bv0.z, bv0.w),
                                  pack2(bv1.x, bv1.y), pack2(bv1.z, bv1.w) };
                    float aa[8] = { av0.x, av0.y, av0.z, av0.w,
                                    av1.x, av1.y, av1.z, av1.w };
                    #pragma unroll
                    for (int r = 0; r < 8; ++r) {
                        ull a2 = pack2(aa[r], aa[r]);
                        fma2(acc[r][0], a2, b2[0]);
                        fma2(acc[r][1], a2, b2[1]);
                        fma2(acc[r][2], a2, b2[2]);
                        fma2(acc[r][3], a2, b2[3]);
                    }
                }
                const int g0 = k0 + 32;
                #pragma unroll
                for (int r = 0; r < 8; ++r) {
                    const int i = il + r;
                    if (i < nt) {
                        float* row = cov + (size_t)(g0 + i) * LDA + g0;
                        if (jl + 7 <= i && jl + 7 < nt) {
                            float4 c0 = *(float4*)(row + jl);
                            float4 c1 = *(float4*)(row + jl + 4);
                            float2 u;
                            u = unpack2(acc[r][0]); c0.x -= u.x; c0.y -= u.y;
                            u = unpack2(acc[r][1]); c0.z -= u.x; c0.w -= u.y;
                            u = unpack2(acc[r][2]); c1.x -= u.x; c1.y -= u.y;
                            u = unpack2(acc[r][3]); c1.z -= u.x; c1.w -= u.y;
                            *(float4*)(row + jl)     = c0;
                            *(float4*)(row + jl + 4) = c1;
                        } else {
                            #pragma unroll
                            for (int s = 0; s < 4; ++s) {
                                float2 u = unpack2(acc[r][s]);
                                int j = jl + 2 * s;
                                if (j     <= i && j     < nt) row[j]     -= u.x;
                                if (j + 1 <= i && j + 1 < nt) row[j + 1] -= u.y;
                            }
                        }
                    }
                }
            }
        }
        __syncthreads();
    }

    // ---- forward substitution: L sol = (y - beta) ----
    float* rhs = Pt;
    for (int i = tid; i < NN; i += NTH) rhs[i] = y[i] - beta;
    __syncthreads();

    for (int kb = 0; kb < 32; ++kb) {
        const int k0 = kb * 32;
        if (tid < 32) {
            const int lane = tid;
            const float* lrow = cov + (size_t)(k0 + lane) * LDA + k0;
            float lr[32];
            #pragma unroll
            for (int w = 0; w < 8; ++w) {
                float4 q = ((const float4*)lrow)[w];
                lr[4*w] = q.x; lr[4*w+1] = q.y; lr[4*w+2] = q.z; lr[4*w+3] = q.w;
            }
            float t = rhs[k0 + lane];
            #pragma unroll
            for (int j = 0; j < 32; ++j) {
                if (lane == j) t /= lr[j];
                float sj = __shfl_sync(0xffffffffu, t, j);
                if (lane > j) t -= sj * lr[j];
            }
            rhs[k0 + lane] = t;
        }
        __syncthreads();
        for (int i = k0 + 32 + tid; i < NN; i += NTH) {
            const float* row = cov + (size_t)i * LDA + k0;
            float acc = 0.f;
            #pragma unroll
            for (int w = 0; w < 8; ++w) {
                float4 c4 = ((const float4*)row)[w];
                acc += c4.x * rhs[k0 + 4*w]     + c4.y * rhs[k0 + 4*w + 1]
                     + c4.z * rhs[k0 + 4*w + 2] + c4.w * rhs[k0 + 4*w + 3];
            }
            rhs[i] -= acc;
        }
        __syncthreads();
    }

    // ---- quad reduction + output ----
    float q = 0.f;
    for (int i = tid; i < NN; i += NTH) q += rhs[i] * rhs[i];
    red[tid] = q;
    __syncthreads();
    for (int s = NTH / 2; s; s >>= 1) {
        if (tid < s) red[tid] += red[tid + s];
        __syncthreads();
    }
    if (tid == 0) {
        float logdet = 2.f * scal[6];
        const float LN2PI = 1.8378770664093453f;
        float ll = -0.5f * (red[0] + logdet + 1024.f * LN2PI);
        out[m] = ll + scal[5];
    }
}

extern "C" void kernel_launch(void* const* d_in, const int* in_sizes, int n_in,
                              void* d_out, int out_size)
{
    (void)in_sizes; (void)n_in; (void)out_size;
    const float* x = (const float*)d_in[0];
    const float* y = (const float*)d_in[1];
    const float* z = (const float*)d_in[2];

    const int smem_bytes = SMEM_FLOATS * (int)sizeof(float);
    cudaFuncSetAttribute(vi_kernel, cudaFuncAttributeMaxDynamicSharedMemorySize, smem_bytes);

    vi_kernel<<<MM, NTH, smem_bytes>>>(
        x, y, z,
        (const float*)d_in[3], (const float*)d_in[4],
        (const float*)d_in[5], (const float*)d_in[6],
        (const float*)d_in[7], (const float*)d_in[8],
        (const float*)d_in[9], (const float*)d_in[10],
        (const float*)d_in[11], (const float*)d_in[12],
        (float*)d_out);
}

// round 3
// speedup vs baseline: 2.0387x; 1.4531x over previous
#include <cuda_runtime.h>
#include <math.h>

#define NN 1024
#define MM 64
#define LDA 1040          // row stride of scratch matrices (floats)
#define PTW 1032          // panel smem row stride (floats)
#define NTH 512

// 64 matrices of 1024x1040 fp32 scratch (static device global: allowed)
__device__ float g_cov[(size_t)MM * NN * LDA];
__device__ float g_rhs[MM * NN];

typedef unsigned long long ull;

__device__ __forceinline__ ull pack2(float lo, float hi) {
    ull r; asm("mov.b64 %0, {%1, %2};" : "=l"(r) : "f"(lo), "f"(hi)); return r;
}
__device__ __forceinline__ void fma2(ull& d, ull a, ull b) {
    asm("fma.rn.f32x2 %0, %1, %2, %0;" : "+l"(d) : "l"(a), "l"(b));
}
__device__ __forceinline__ float2 unpack2(ull v) {
    float2 f; asm("mov.b64 {%0, %1}, %2;" : "=f"(f.x), "=f"(f.y) : "l"(v)); return f;
}
__device__ __forceinline__ void cluster_sync_() {
    asm volatile("barrier.cluster.arrive.aligned;" ::: "memory");
    asm volatile("barrier.cluster.wait.aligned;" ::: "memory");
}

__device__ __forceinline__ float sp_(float x) {
    return fmaxf(x, 0.f) + log1pf(expf(-fabsf(x))) + 1e-7f;
}
__device__ __forceinline__ float log_normal_(float v, float mean, float s, float eps) {
    const float C = -0.91893853320467274178f;
    float d = v - mean;
    return -d * d / (2.f * s * s + eps) - logf(s) + C;
}
__device__ __forceinline__ float log_lognormal_(float v, float mean, float s, float eps) {
    const float C = -0.91893853320467274178f;
    float lv = logf(v);
    float d = lv - mean;
    return -d * d / (2.f * s * s + eps) - lv - logf(s) + C;
}

// smem layout (floats):
//   Pt [32*PTW], Lkk [32*33], rinv[32], scal[8], red[NTH], rsol[32]
#define SMEM_FLOATS (32 * PTW + 32 * 33 + 32 + 8 + NTH + 32)

extern "C" __global__ void __launch_bounds__(NTH, 1) __cluster_dims__(2, 1, 1)
vi_kernel(const float* __restrict__ x, const float* __restrict__ y,
          const float* __restrict__ z,
          const float* qbm, const float* qbs, const float* qsm, const float* qss,
          const float* qem, const float* qes, const float* qzm, const float* qzs,
          const float* qnm, const float* qns, float* __restrict__ out)
{
    extern __shared__ float sm[];
    float* Pt   = sm;
    float* Lkk  = sm + 32 * PTW;
    float* rinv = Lkk + 32 * 33;
    float* scal = rinv + 32;
    float* red  = scal + 8;
    float* rsol = red + NTH;

    const int tid  = threadIdx.x;
    const int m    = blockIdx.x >> 1;
    const int rank = blockIdx.x & 1;
    float* cov = g_cov + (size_t)m * NN * LDA;
    float* rhs = g_rhs + m * NN;

    // ---- scalar terms (thread 0 of each CTA, redundant) ----
    if (tid == 0) {
        float s0 = sp_(sqrtf(logf(2.f)));
        float z0 = z[m * 5 + 0], z1 = z[m * 5 + 1], z2 = z[m * 5 + 2];
        float z3 = z[m * 5 + 3], z4 = z[m * 5 + 4];
        float sps = sp_(*qss), spb = sp_(*qbs), spe = sp_(*qes);
        float spz = sp_(*qzs), spn = sp_(*qns);
        float sigma2 = expf(z0 * sps + *qsm);
        float beta   = z1 * spb + *qbm;
        float eta    = expf(z2 * spe + *qem);
        float lsZ    = expf(z3 * spz + *qzm);
        float lsN    = expf(z4 * spn + *qnm);
        float lp = log_normal_(beta, 0.f, 1.f, 1e-5f)
                 + log_lognormal_(sigma2, 1.f, s0, 1e-6f)
                 + log_lognormal_(eta,    1.f, s0, 1e-6f)
                 + log_lognormal_(lsZ,    1.f, s0, 1e-6f)
                 + log_lognormal_(lsN,    1.f, s0, 1e-6f);
        float lq = log_normal_(beta, *qbm, spb, 1e-5f)
                 + log_lognormal_(sigma2, *qsm, sps, 1e-6f)
                 + log_lognormal_(eta,    *qem, spe, 1e-6f)
                 + log_lognormal_(lsZ,    *qzm, spz, 1e-6f)
                 + log_lognormal_(lsN,    *qnm, spn, 1e-6f);
        scal[0] = beta; scal[1] = sigma2; scal[2] = eta;
        scal[3] = lsZ;  scal[4] = lsN;    scal[5] = lp - lq;
        scal[6] = 0.f;
    }
    __syncthreads();
    const float beta = scal[0], sigma2 = scal[1], eta = scal[2];

    // ---- stage scaled x into smem (both CTAs, full) ----
    {
        float lsZ = scal[3], lsN = scal[4];
        float* xs0 = Pt;
        float* xs1 = Pt + NN;
        for (int i = tid; i < NN; i += NTH) {
            xs0[i] = x[2 * i]     / lsZ;
            xs1[i] = x[2 * i + 1] / lsN;
        }
    }
    __syncthreads();

    // ---- build lower-triangular cov, rows split by parity ----
    {
        const float* xs0 = Pt;
        const float* xs1 = Pt + NN;
        for (int it = tid; it < NN / 2; it += NTH) {
            int i = 2 * it + rank;
            float xi0 = xs0[i], xi1 = xs1[i];
            float* row = cov + (size_t)i * LDA;
            for (int j = 0; j < i; ++j) {
                float d0 = xi0 - xs0[j];
                float d1 = xi1 - xs1[j];
                row[j] = eta * __expf(-0.5f * (d0 * d0 + d1 * d1));
            }
            row[i] = eta + sigma2;
        }
    }
    cluster_sync_();

    // ---- blocked Cholesky, NB=32, 32 steps, 2 CTAs per matrix ----
    for (int kb = 0; kb < 32; ++kb) {
        const int k0 = kb * 32;

        // load diag block (lower) into smem, zero upper (both CTAs)
        for (int idx = tid; idx < 1024; idx += NTH) {
            int r = idx >> 5, c = idx & 31;
            Lkk[r * 33 + c] = (c <= r) ? cov[(size_t)(k0 + r) * LDA + k0 + c] : 0.f;
        }
        __syncthreads();

        // factor 32x32 diag block redundantly (warp 0 of each CTA)
        if (tid < 32) {
            const int lane = tid;
            float a[32];
            #pragma unroll
            for (int j = 0; j < 32; ++j) a[j] = Lkk[lane * 33 + j];
            #pragma unroll
            for (int j = 0; j < 32; ++j) {
                float dj = __shfl_sync(0xffffffffu, a[j], j);
                float sj = sqrtf(dj);
                float lrj = (lane == j) ? sj : a[j] / sj;
                a[j] = lrj;
                #pragma unroll
                for (int c = j + 1; c < 32; ++c) {
                    float lcj = __shfl_sync(0xffffffffu, lrj, c);
                    a[c] -= lrj * lcj;
                }
            }
            #pragma unroll
            for (int j = 0; j < 32; ++j)
                if (j <= lane) Lkk[lane * 33 + j] = a[j];
            rinv[lane] = 1.f / a[lane];
            float ld = logf(a[lane]);
            #pragma unroll
            for (int o = 16; o; o >>= 1) ld += __shfl_xor_sync(0xffffffffu, ld, o);
            if (lane == 0) scal[6] += ld;
        }
        __syncthreads();

        const int nt = NN - k0 - 32;

        // ---- panel solve: own-parity rows -> cov (global) + own Pt cols ----
        if (nt > 0) {
            for (int it2 = tid; 2 * it2 + rank < nt; it2 += NTH) {
                int it = 2 * it2 + rank;
                const float* r1 = cov + (size_t)(k0 + 32 + it) * LDA + k0;
                float a1[32];
                #pragma unroll
                for (int w = 0; w < 8; ++w) {
                    float4 q1 = ((const float4*)r1)[w];
                    a1[4*w] = q1.x; a1[4*w+1] = q1.y; a1[4*w+2] = q1.z; a1[4*w+3] = q1.w;
                }
                #pragma unroll
                for (int j = 0; j < 32; ++j) {
                    float s1 = a1[j];
                    #pragma unroll
                    for (int p = 0; p < j; ++p)
                        s1 -= a1[p] * Lkk[j * 33 + p];
                    a1[j] = s1 * rinv[j];
                }
                float* wr = cov + (size_t)(k0 + 32 + it) * LDA + k0;
                #pragma unroll
                for (int w = 0; w < 8; ++w)
                    ((float4*)wr)[w] = make_float4(a1[4*w], a1[4*w+1], a1[4*w+2], a1[4*w+3]);
                #pragma unroll
                for (int p = 0; p < 32; ++p) Pt[p * PTW + it] = a1[p];
            }
        }
        cluster_sync_();   // peer panel rows visible (and L1 invalidated)

        if (nt > 0) {
            // write factored diag back to cov (rank 0 only; only fwd-subst reads it)
            if (rank == 0) {
                for (int idx = tid; idx < 1024; idx += NTH) {
                    int r = idx >> 5, c = idx & 31;
                    if (c <= r) cov[(size_t)(k0 + r) * LDA + k0 + c] = Lkk[r * 33 + c];
                }
            }
            // fill peer-parity rows of Pt from global cov
            for (int it2 = tid; 2 * it2 + (1 - rank) < nt; it2 += NTH) {
                int it = 2 * it2 + (1 - rank);
                const float* r1 = cov + (size_t)(k0 + 32 + it) * LDA + k0;
                #pragma unroll
                for (int w = 0; w < 8; ++w) {
                    float4 q1 = ((const float4*)r1)[w];
                    Pt[(4*w    ) * PTW + it] = q1.x;
                    Pt[(4*w + 1) * PTW + it] = q1.y;
                    Pt[(4*w + 2) * PTW + it] = q1.z;
                    Pt[(4*w + 3) * PTW + it] = q1.w;
                }
            }
            __syncthreads();

            // ---- trailing SYRK: 4 worker groups across the 2 CTAs ----
            const int ntile = (nt + 127) >> 7;
            const int npair = ntile * (ntile + 1) / 2;
            const int w4  = rank * 2 + (tid >> 8);   // 0..3
            const int t   = tid & 255;
            const int tx = t & 15, ty = t >> 4;
            for (int pair = w4; pair < npair; pair += 4) {
                int tjb = 0, rem = pair;
                while (rem >= ntile - tjb) { rem -= ntile - tjb; ++tjb; }
                int tib = tjb + rem;

                const int il = tib * 128 + ty * 8;
                const int jl = tjb * 128 + tx * 8;
                ull acc[8][4];
                #pragma unroll
                for (int r = 0; r < 8; ++r)
                    #pragma unroll
                    for (int s = 0; s < 4; ++s) acc[r][s] = 0ull;

                #pragma unroll 8
                for (int p = 0; p < 32; ++p) {
                    const float4* bp = (const float4*)(Pt + p * PTW);
                    float4 av0 = bp[il >> 2], av1 = bp[(il >> 2) + 1];
                    float4 bv0 = bp[jl >> 2], bv1 = bp[(jl >> 2) + 1];
                    ull b2[4] = { pack2(bv0.x, bv0.y), pack2(bv0.z, bv0.w),
                                  pack2(bv1.x, bv1.y), pack2(bv1.z, bv1.w) };
                    float aa[8] = { av0.x, av0.y, av0.z, av0.w,
                                    av1.x, av1.y, av1.z, av1.w };
                    #pragma unroll
                    for (int r = 0; r < 8; ++r) {
                        ull a2 = pack2(aa[r], aa[r]);
                        fma2(acc[r][0], a2, b2[0]);
                        fma2(acc[r][1], a2, b2[1]);
                        fma2(acc[r][2], a2, b2[2]);
                        fma2(acc[r][3], a2, b2[3]);
                    }
                }
                const int g0 = k0 + 32;
                #pragma unroll
                for (int r = 0; r < 8; ++r) {
                    const int i = il + r;
                    if (i < nt) {
                        float* row = cov + (size_t)(g0 + i) * LDA + g0;
                        if (jl + 7 <= i && jl + 7 < nt) {
                            float4 c0 = *(float4*)(row + jl);
                            float4 c1 = *(float4*)(row + jl + 4);
                            float2 u;
                            u = unpack2(acc[r][0]); c0.x -= u.x; c0.y -= u.y;
                            u = unpack2(acc[r][1]); c0.z -= u.x; c0.w -= u.y;
                            u = unpack2(acc[r][2]); c1.x -= u.x; c1.y -= u.y;
                            u = unpack2(acc[r][3]); c1.z -= u.x; c1.w -= u.y;
                            *(float4*)(row + jl)     = c0;
                            *(float4*)(row + jl + 4) = c1;
                        } else {
                            #pragma unroll
                            for (int s = 0; s < 4; ++s) {
                                float2 u = unpack2(acc[r][s]);
                                int j = jl + 2 * s;
                                if (j     <= i && j     < nt) row[j]     -= u.x;
                                if (j + 1 <= i && j + 1 < nt) row[j + 1] -= u.y;
                            }
                        }
                    }
                }
            }
        } else {
            // kb == 31: still store diag back
            if (rank == 0) {
                for (int idx = tid; idx < 1024; idx += NTH) {
                    int r = idx >> 5, c = idx & 31;
                    if (c <= r) cov[(size_t)(k0 + r) * LDA + k0 + c] = Lkk[r * 33 + c];
                }
            }
        }
        cluster_sync_();
    }

    // ---- forward substitution: L sol = (y - beta), rhs in global ----
    if (rank == 0)
        for (int i = tid; i < NN; i += NTH) rhs[i] = y[i] - beta;

    for (int kb = 0; kb < 32; ++kb) {
        const int k0 = kb * 32;
        cluster_sync_();
        // triangular solve of 32 block, redundant in both CTAs
        if (tid < 32) {
            const int lane = tid;
            const float* lrow = cov + (size_t)(k0 + lane) * LDA + k0;
            float lr[32];
            #pragma unroll
            for (int w = 0; w < 8; ++w) {
                float4 q = ((const float4*)lrow)[w];
                lr[4*w] = q.x; lr[4*w+1] = q.y; lr[4*w+2] = q.z; lr[4*w+3] = q.w;
            }
            float t = rhs[k0 + lane];
            #pragma unroll
            for (int j = 0; j < 32; ++j) {
                if (lane == j) t /= lr[j];
                float sj = __shfl_sync(0xffffffffu, t, j);
                if (lane > j) t -= sj * lr[j];
            }
            rsol[lane] = t;
            if (rank == 0) rhs[k0 + lane] = t;
        }
        __syncthreads();
        // GEMV update: own-parity rows
        for (int i = k0 + 32 + tid; i < NN; i += NTH) {
            if ((i & 1) != rank) continue;
            const float* row = cov + (size_t)i * LDA + k0;
            float acc = 0.f;
            #pragma unroll
            for (int w = 0; w < 8; ++w) {
                float4 c4 = ((const float4*)row)[w];
                acc += c4.x * rsol[4*w]     + c4.y * rsol[4*w + 1]
                     + c4.z * rsol[4*w + 2] + c4.w * rsol[4*w + 3];
            }
            rhs[i] -= acc;
        }
    }
    cluster_sync_();

    // ---- quad reduction + output (rank 0) ----
    if (rank == 0) {
        float q = 0.f;
        for (int i = tid; i < NN; i += NTH) { float v = rhs[i]; q += v * v; }
        red[tid] = q;
        __syncthreads();
        for (int s = NTH / 2; s; s >>= 1) {
            if (tid < s) red[tid] += red[tid + s];
            __syncthreads();
        }
        if (tid == 0) {
            float logdet = 2.f * scal[6];
            const float LN2PI = 1.8378770664093453f;
            float ll = -0.5f * (red[0] + logdet + 1024.f * LN2PI);
            out[m] = ll + scal[5];
        }
    }
    cluster_sync_();   // keep peer alive until rank0 done reading rhs
}

extern "C" void kernel_launch(void* const* d_in, const int* in_sizes, int n_in,
                              void* d_out, int out_size)
{
    (void)in_sizes; (void)n_in; (void)out_size;
    const float* x = (const float*)d_in[0];
    const float* y = (const float*)d_in[1];
    const float* z = (const float*)d_in[2];

    const int smem_bytes = SMEM_FLOATS * (int)sizeof(float);
    cudaFuncSetAttribute(vi_kernel, cudaFuncAttributeMaxDynamicSharedMemorySize, smem_bytes);

    vi_kernel<<<2 * MM, NTH, smem_bytes>>>(
        x, y, z,
        (const float*)d_in[3], (const float*)d_in[4],
        (const float*)d_in[5], (const float*)d_in[6],
        (const float*)d_in[7], (const float*)d_in[8],
        (const float*)d_in[9], (const float*)d_in[10],
        (const float*)d_in[11], (const float*)d_in[12],
        (float*)d_out);
}